// round 14
// baseline (speedup 1.0000x reference)
#include <cuda_runtime.h>
#include <cuda_fp16.h>
#include <math.h>
#include <stdint.h>

#define FDIM 512
#define DDIM 128
#define NMAX 50048
#define EPSF 1e-5f

// Scratch (allocation-free rule: device globals)
__device__ float g_x[(size_t)NMAX * DDIM];      // encoded node features
__device__ unsigned g_Wh[256 * 128];            // W_enc fp16, word = k-pair, [k2][n]

__device__ __forceinline__ void mma16h(float* c, unsigned a0, unsigned a1,
                                       unsigned a2, unsigned a3,
                                       unsigned b0, unsigned b1) {
    asm volatile(
        "mma.sync.aligned.m16n8k16.row.col.f32.f16.f16.f32 "
        "{%0,%1,%2,%3},{%4,%5,%6,%7},{%8,%9},{%0,%1,%2,%3};"
        : "+f"(c[0]), "+f"(c[1]), "+f"(c[2]), "+f"(c[3])
        : "r"(a0), "r"(a1), "r"(a2), "r"(a3), "r"(b0), "r"(b1));
}
__device__ __forceinline__ void ldsm4(unsigned* r, uint32_t addr) {
    asm volatile(
        "ldmatrix.sync.aligned.m8n8.x4.shared.b16 {%0,%1,%2,%3}, [%4];"
        : "=r"(r[0]), "=r"(r[1]), "=r"(r[2]), "=r"(r[3]) : "r"(addr));
}
__device__ __forceinline__ float clipf(float v) {
    return fminf(1.0f, fmaxf(-1.0f, v));
}
__device__ __forceinline__ unsigned pack2h(float lo, float hi) {
    __half2 h = __floats2half2_rn(lo, hi);
    return *(unsigned*)&h;
}
__device__ __forceinline__ uint32_t smem_u32(const void* p) {
    uint32_t a;
    asm("{ .reg .u64 t; cvta.to.shared.u64 t, %1; cvt.u32.u64 %0, t; }"
        : "=r"(a) : "l"(p));
    return a;
}
__device__ __forceinline__ void cpasync16(uint32_t dst, const void* src, int szr) {
    asm volatile("cp.async.ca.shared.global [%0], [%1], 16, %2;"
                 :: "r"(dst), "l"(src), "r"(szr) : "memory");
}
#define CP_COMMIT() asm volatile("cp.async.commit_group;" ::: "memory")
#define CP_WAIT1()  asm volatile("cp.async.wait_group 1;" ::: "memory")

// ---------------------------------------------------------------------------
// Kernel 0: pack W_enc to fp16 k-pair words over ALL K=512 (256 k2-rows).
// (unchanged from R13)
// ---------------------------------------------------------------------------
__global__ void prep_w(const float* __restrict__ W) {
    int i = blockIdx.x * blockDim.x + threadIdx.x;
    if (i < 256 * 128) {
        int k2 = i >> 7, n = i & 127;
        g_Wh[i] = pack2h(W[2 * k2 * 128 + n], W[(2 * k2 + 1) * 128 + n]);
    }
}

// ---------------------------------------------------------------------------
// Kernel 1: encoder (unchanged from R13 — M=64 tile, 256 thr, 3 CTAs/SM)
// ---------------------------------------------------------------------------
#define ENC_A_BYTES (64 * 20 * 4)                     // 5120
#define ENC_B_BYTES (16 * 128 * 4)                    // 8192
#define ENC_SMEM    (3 * (ENC_A_BYTES + ENC_B_BYTES)) // 39936

__global__ __launch_bounds__(256, 3)
void encoder_h3(const float* __restrict__ pos, const float* __restrict__ bias,
                int N) {
    extern __shared__ unsigned char sm[];
    unsigned* As = (unsigned*)sm;
    unsigned* Bs = (unsigned*)(sm + 3 * ENC_A_BYTES);
    const uint32_t smb = smem_u32(sm);

    const int t = threadIdx.x, lane = t & 31, w = t >> 5;
    const int lm = lane >> 2, lk = lane & 3;
    const int m0 = (w >> 2) * 32, n0 = (w & 3) * 32;
    const int m0g = blockIdx.x * 64;

    const int arow = t >> 2, aq = t & 3;
    const bool aok = (m0g + arow) < N;
    const float* ap = pos + (size_t)(m0g + arow) * FDIM + aq * 8;
    const int asoff = arow * 20 + aq * 4;
    const int bk2 = t >> 4, bn8 = (t & 15) * 8;
    const int bsw = 8 * (bk2 & 3);
    const uint32_t bdst0 = smb + 3 * ENC_A_BYTES + (bk2 * 128 + (bn8 ^ bsw)) * 4;
    const uint32_t bdst1 = smb + 3 * ENC_A_BYTES + (bk2 * 128 + ((bn8 + 4) ^ bsw)) * 4;
    const unsigned* bsrc = g_Wh + bk2 * 128 + bn8;

    float acc[2][4][4];
#pragma unroll
    for (int mf = 0; mf < 2; mf++)
#pragma unroll
        for (int nf = 0; nf < 4; nf++)
#pragma unroll
            for (int r = 0; r < 4; r++) acc[mf][nf][r] = 0.0f;

    float4 rb0[2], rb1[2];
    auto ldgA = [&](float4* r, int kt) {
        if (aok) {
            r[0] = *(const float4*)(ap + kt * 32);
            r[1] = *(const float4*)(ap + kt * 32 + 4);
        } else {
            r[0] = make_float4(0, 0, 0, 0);
            r[1] = make_float4(0, 0, 0, 0);
        }
    };
    auto stsA = [&](int s, const float4* r) {
        uint4 u = make_uint4(pack2h(r[0].x, r[0].y), pack2h(r[0].z, r[0].w),
                             pack2h(r[1].x, r[1].y), pack2h(r[1].z, r[1].w));
        *(uint4*)&As[s * 1280 + asoff] = u;
    };
    auto cpB = [&](int s, int kt) {
        cpasync16(bdst0 + s * ENC_B_BYTES, bsrc + kt * 16 * 128, 16);
        cpasync16(bdst1 + s * ENC_B_BYTES, bsrc + kt * 16 * 128 + 4, 16);
    };

    ldgA(rb0, 0); ldgA(rb1, 1);
    cpB(0, 0); CP_COMMIT();
    cpB(1, 1); CP_COMMIT();
    stsA(0, rb0); stsA(1, rb1);
    ldgA(rb0, 2); ldgA(rb1, 3);

    for (int kt = 0; kt < 16; kt++) {
        const int s = kt % 3;
        CP_WAIT1();
        __syncthreads();
        if (kt + 2 < 16) {
            float4* rb = (kt & 1) ? rb1 : rb0;
            stsA((kt + 2) % 3, rb);
            cpB((kt + 2) % 3, kt + 2);
            if (kt + 4 < 16) ldgA(rb, kt + 4);
        }
        CP_COMMIT();

        const unsigned* Asp = As + s * 1280;
        const unsigned* Bsp = Bs + s * 2048;
#pragma unroll
        for (int ks = 0; ks < 2; ks++) {
            const int k20 = ks * 8;
            const int sw = 8 * lk;
            unsigned a[2][4];
#pragma unroll
            for (int mf = 0; mf < 2; mf++) {
                int rb_ = m0 + mf * 16;
                a[mf][0] = Asp[(rb_ + lm) * 20 + k20 + lk];
                a[mf][1] = Asp[(rb_ + lm + 8) * 20 + k20 + lk];
                a[mf][2] = Asp[(rb_ + lm) * 20 + k20 + lk + 4];
                a[mf][3] = Asp[(rb_ + lm + 8) * 20 + k20 + lk + 4];
            }
            unsigned b[4][2];
#pragma unroll
            for (int nf = 0; nf < 4; nf++) {
                int cb = n0 + nf * 8;
                b[nf][0] = Bsp[(k20 + lk) * 128 + ((cb + lm) ^ sw)];
                b[nf][1] = Bsp[(k20 + lk + 4) * 128 + ((cb + lm) ^ sw)];
            }
#pragma unroll
            for (int mf = 0; mf < 2; mf++)
#pragma unroll
                for (int nf = 0; nf < 4; nf++)
                    mma16h(acc[mf][nf], a[mf][0], a[mf][1], a[mf][2], a[mf][3],
                           b[nf][0], b[nf][1]);
        }
    }

#pragma unroll
    for (int mf = 0; mf < 2; mf++) {
        int r0 = m0g + m0 + mf * 16 + lm;
#pragma unroll
        for (int nf = 0; nf < 4; nf++) {
            int c = n0 + nf * 8 + 2 * lk;
            float b0 = __ldg(bias + c), b1 = __ldg(bias + c + 1);
            float2 v0, v1;
            v0.x = clipf(acc[mf][nf][0] + b0);
            v0.y = clipf(acc[mf][nf][1] + b1);
            v1.x = clipf(acc[mf][nf][2] + b0);
            v1.y = clipf(acc[mf][nf][3] + b1);
            *(float2*)&g_x[(size_t)r0 * 128 + c]       = v0;
            *(float2*)&g_x[(size_t)(r0 + 8) * 128 + c] = v1;
        }
    }
}

// ---------------------------------------------------------------------------
// Kernel 2: fused per-hyperedge pipeline, 16 edges/iter, FP16 mma m16n8k16.
// R14: fragment loads via ldmatrix.x4 (5 LDSM + 2 LDS per k-step vs 22 LDS).
// Cheb matrices relaid to [c][k2] stride 68 (same conflict-free stride as Gw).
// smem layout (dynamic, 152576 B):
//   Acs word[128*68] @0      : Cheb A fp16, [c][k2] stride 68
//   Bcs word[128*68] @34816  : Cheb B fp16, same
//   Gw  word[128*68] @69632  : g fp16, [row][k2] stride 68
//   Hs  float[128*136]@69632 : (union w/ Gw) h fp32, stride 136
//   Sw  word[16*68]  @139264 : S fp16
//   Qsm float[16*136]@143616 : q = S@B + chebb
//   red float[16*4]  @152320
// ---------------------------------------------------------------------------
#define ESMEM 152576

__global__ __launch_bounds__(512, 1)
void edge_mma(const int* __restrict__ members, const float* __restrict__ chebW,
              const float* __restrict__ gamma_, const float* __restrict__ beta_,
              const float* __restrict__ alpha_, const float* __restrict__ chebb,
              const float* __restrict__ linW, const float* __restrict__ linb,
              float* __restrict__ out, int E) {
    extern __shared__ unsigned char esm[];
    unsigned* Acs = (unsigned*)esm;
    unsigned* Bcs = (unsigned*)(esm + 34816);
    unsigned* Gw  = (unsigned*)(esm + 69632);
    float*    Hs  = (float*)(esm + 69632);
    unsigned* Sw  = (unsigned*)(esm + 139264);
    float*    Qsm = (float*)(esm + 143616);
    float*    red = (float*)(esm + 152320);
    const uint32_t smb = smem_u32(esm);

    const int t = threadIdx.x;
    const int lane = t & 31, w = t >> 5;
    const int lm = lane >> 2, lk = lane & 3;

    // ---- Cheb combine into [c][k2] stride-68 fp16 layout ----
    // thread: c = t&127 (coalesced chebW reads), k2 quad = (t>>7)*4 + 16*kq
    {
        const int c = t & 127;
#pragma unroll
        for (int kq = 0; kq < 4; kq++) {
            int k2q = (t >> 7) * 4 + kq * 16;
            unsigned ua[4], ub[4];
#pragma unroll
            for (int j = 0; j < 4; j++) {
                int d0 = 2 * (k2q + j);
                float w00 = __ldg(chebW + d0 * 128 + c);
                float w01 = __ldg(chebW + 16384 + d0 * 128 + c);
                float w02 = __ldg(chebW + 32768 + d0 * 128 + c);
                float w10 = __ldg(chebW + (d0 + 1) * 128 + c);
                float w11 = __ldg(chebW + 16384 + (d0 + 1) * 128 + c);
                float w12 = __ldg(chebW + 32768 + (d0 + 1) * 128 + c);
                float A0 = w00 + w01 * (1.0f/7.0f) - w02 * (47.0f/49.0f);
                float A1 = w10 + w11 * (1.0f/7.0f) - w12 * (47.0f/49.0f);
                float B0 = -w01 * (1.0f/7.0f) + w02 * (12.0f/49.0f);
                float B1 = -w11 * (1.0f/7.0f) + w12 * (12.0f/49.0f);
                ua[j] = pack2h(A0, A1);
                ub[j] = pack2h(B0, B1);
            }
            *(uint4*)&Acs[c * 68 + k2q] = make_uint4(ua[0], ua[1], ua[2], ua[3]);
            *(uint4*)&Bcs[c * 68 + k2q] = make_uint4(ub[0], ub[1], ub[2], ub[3]);
        }
    }

    const int c4 = t & 31;
    const float4 ga4 = *(const float4*)(gamma_ + 4 * c4);
    const float4 be4 = *(const float4*)(beta_  + 4 * c4);
    const float4 al4 = *(const float4*)(alpha_ + 4 * c4);

    const int d = t & 127, quarter = t >> 7;
    const float lw0 = linW[d], lw1 = linW[128 + d];
    const float lb = __ldg(linb);

    const int m0 = (w >> 2) * 32, n0 = (w & 3) * 32, nq0 = w * 8;
    const int nIter = (E + 15) >> 4;

    // ldmatrix row addresses (bytes)
    const uint32_t gwb = smb + 69632, swb = smb + 139264;
    const uint32_t aaddr0 = gwb + ((m0 + (lane & 15)) * 68 + ((lane >> 4) << 2)) * 4;
    const uint32_t aaddr1 = aaddr0 + 16 * 68 * 4;
    const uint32_t baddr  = smb + ((n0 + lane) * 68) * 4;
    const uint32_t saddr  = swb + ((lane & 15) * 68 + ((lane >> 4) << 2)) * 4;

    __syncthreads();   // Acs/Bcs ready

    for (int it = blockIdx.x; it < nIter; it += gridDim.x) {
        const int ebase = it * 16;

        const int el = w;
        const int e = ebase + el;
        int mreg = 0;
        if (lane < 8 && e < E) mreg = __ldg(&members[e * 8 + lane]);

        // ---- stage A: gather + GraphNorm -> fp16 Gw / Sw ----
        {
            unsigned* grow = Gw + el * 8 * 68 + 2 * c4;
            unsigned* srow = Sw + el * 68 + 2 * c4;
            if (e < E) {
                float4 xv[8];
#pragma unroll
                for (int i = 0; i < 8; i++) {
                    int node = __shfl_sync(0xffffffffu, mreg, i);
                    xv[i] = *(const float4*)(g_x + (size_t)node * 128 + 4 * c4);
                }
                float4 mean = make_float4(0, 0, 0, 0);
#pragma unroll
                for (int i = 0; i < 8; i++) {
                    mean.x += xv[i].x; mean.y += xv[i].y;
                    mean.z += xv[i].z; mean.w += xv[i].w;
                }
                mean.x *= 0.125f; mean.y *= 0.125f;
                mean.z *= 0.125f; mean.w *= 0.125f;
                float4 am = make_float4(al4.x * mean.x, al4.y * mean.y,
                                        al4.z * mean.z, al4.w * mean.w);
                float4 var = make_float4(0, 0, 0, 0);
#pragma unroll
                for (int i = 0; i < 8; i++) {
                    xv[i].x -= am.x; xv[i].y -= am.y;
                    xv[i].z -= am.z; xv[i].w -= am.w;
                    var.x += xv[i].x * xv[i].x; var.y += xv[i].y * xv[i].y;
                    var.z += xv[i].z * xv[i].z; var.w += xv[i].w * xv[i].w;
                }
                float4 inv;
                inv.x = ga4.x * rsqrtf(var.x * 0.125f + EPSF);
                inv.y = ga4.y * rsqrtf(var.y * 0.125f + EPSF);
                inv.z = ga4.z * rsqrtf(var.z * 0.125f + EPSF);
                inv.w = ga4.w * rsqrtf(var.w * 0.125f + EPSF);
#pragma unroll
                for (int i = 0; i < 8; i++) {
                    uint2 u;
                    u.x = pack2h(xv[i].x * inv.x + be4.x, xv[i].y * inv.y + be4.y);
                    u.y = pack2h(xv[i].z * inv.z + be4.z, xv[i].w * inv.w + be4.w);
                    *(uint2*)(grow + i * 68) = u;
                }
                uint2 su;
                su.x = pack2h(inv.x * 8.0f * mean.x * (1.0f - al4.x) + 8.0f * be4.x,
                              inv.y * 8.0f * mean.y * (1.0f - al4.y) + 8.0f * be4.y);
                su.y = pack2h(inv.z * 8.0f * mean.z * (1.0f - al4.z) + 8.0f * be4.z,
                              inv.w * 8.0f * mean.w * (1.0f - al4.w) + 8.0f * be4.w);
                *(uint2*)srow = su;
            } else {
                uint2 z = make_uint2(0, 0);
#pragma unroll
                for (int i = 0; i < 8; i++) *(uint2*)(grow + i * 68) = z;
                *(uint2*)srow = z;
            }
        }
        __syncthreads();

        // ---- stage B: fp16 MMAs via ldmatrix fragments ----
        float acc[2][4][4];
        float qac[4];
#pragma unroll
        for (int mf = 0; mf < 2; mf++)
#pragma unroll
            for (int nf = 0; nf < 4; nf++)
#pragma unroll
                for (int r = 0; r < 4; r++) acc[mf][nf][r] = 0.0f;
#pragma unroll
        for (int r = 0; r < 4; r++) qac[r] = 0.0f;

#pragma unroll
        for (int ks = 0; ks < 8; ks++) {
            unsigned a0[4], a1[4], bl[4], bh[4], sv[4];
            ldsm4(a0, aaddr0 + ks * 32);
            ldsm4(a1, aaddr1 + ks * 32);
            ldsm4(bl, baddr + ks * 32);
            ldsm4(bh, baddr + ks * 32 + 16);
            ldsm4(sv, saddr + ks * 32);
            unsigned qb0 = Bcs[(nq0 + lm) * 68 + ks * 8 + lk];
            unsigned qb1 = Bcs[(nq0 + lm) * 68 + ks * 8 + lk + 4];
#pragma unroll
            for (int nf = 0; nf < 4; nf++) {
                mma16h(acc[0][nf], a0[0], a0[1], a0[2], a0[3], bl[nf], bh[nf]);
                mma16h(acc[1][nf], a1[0], a1[1], a1[2], a1[3], bl[nf], bh[nf]);
            }
            mma16h(qac, sv[0], sv[1], sv[2], sv[3], qb0, qb1);
        }
        {
            int c = nq0 + 2 * lk;
            float cb0 = __ldg(chebb + c), cb1 = __ldg(chebb + c + 1);
            Qsm[lm * 136 + c]           = qac[0] + cb0;
            Qsm[lm * 136 + c + 1]       = qac[1] + cb1;
            Qsm[(lm + 8) * 136 + c]     = qac[2] + cb0;
            Qsm[(lm + 8) * 136 + c + 1] = qac[3] + cb1;
        }
        __syncthreads();

        // ---- stage C: h = clip(acc + Q[e][c]) -> Hs (reuses Gw space) ----
#pragma unroll
        for (int mf = 0; mf < 2; mf++) {
            int rb = m0 + mf * 16 + lm;
            int e0 = rb >> 3;
            int e1 = (rb + 8) >> 3;
#pragma unroll
            for (int nf = 0; nf < 4; nf++) {
                int c = n0 + nf * 8 + 2 * lk;
                float2 q0 = *(const float2*)&Qsm[e0 * 136 + c];
                float2 q1 = *(const float2*)&Qsm[e1 * 136 + c];
                float2 v0, v1;
                v0.x = clipf(acc[mf][nf][0] + q0.x);
                v0.y = clipf(acc[mf][nf][1] + q0.y);
                v1.x = clipf(acc[mf][nf][2] + q1.x);
                v1.y = clipf(acc[mf][nf][3] + q1.y);
                *(float2*)&Hs[rb * 136 + c]       = v0;
                *(float2*)&Hs[(rb + 8) * 136 + c] = v1;
            }
        }
        __syncthreads();

        // ---- stage D: pooling + linear head + sigmoid (4 edges / thread) ----
        float contrib[4];
#pragma unroll
        for (int j = 0; j < 4; j++) {
            int elj = quarter * 4 + j;
            float mx = -2.0f, mn = 2.0f, ss = 0.0f;
#pragma unroll
            for (int i = 0; i < 8; i++) {
                float h = Hs[(elj * 8 + i) * 136 + d];
                mx = fmaxf(mx, h);
                mn = fminf(mn, h);
                ss += h * h;
            }
            contrib[j] = (mx - mn) * lw0 + sqrtf(ss * 0.125f) * lw1;
        }
#pragma unroll
        for (int j = 0; j < 4; j++) {
            float v = contrib[j];
            v += __shfl_xor_sync(0xffffffffu, v, 16);
            v += __shfl_xor_sync(0xffffffffu, v, 8);
            v += __shfl_xor_sync(0xffffffffu, v, 4);
            v += __shfl_xor_sync(0xffffffffu, v, 2);
            v += __shfl_xor_sync(0xffffffffu, v, 1);
            if (lane == 0) red[(quarter * 4 + j) * 4 + (w & 3)] = v;
        }
        __syncthreads();
        if (t < 16) {
            int eo = ebase + t;
            if (eo < E) {
                float* r = red + t * 4;
                float logit = r[0] + r[1] + r[2] + r[3] + lb;
                out[eo] = 1.0f / (1.0f + expf(-logit));
            }
        }
        __syncthreads();   // protect smem before next iteration
    }
}

// ---------------------------------------------------------------------------
extern "C" void kernel_launch(void* const* d_in, const int* in_sizes, int n_in,
                              void* d_out, int out_size) {
    const float* pos   = (const float*)d_in[0];
    const float* Wenc  = (const float*)d_in[1];
    const float* benc  = (const float*)d_in[2];
    const float* gam   = (const float*)d_in[3];
    const float* bet   = (const float*)d_in[4];
    const float* alp   = (const float*)d_in[5];
    const float* chebW = (const float*)d_in[6];
    const float* chebb = (const float*)d_in[7];
    const float* linW  = (const float*)d_in[8];
    const float* linb  = (const float*)d_in[9];
    const int*   membs = (const int*)d_in[10];

    int N = in_sizes[0] / FDIM;   // 50000
    int E = in_sizes[10] / 8;     // 20000

    prep_w<<<128, 256>>>(Wenc);

    cudaFuncSetAttribute(encoder_h3, cudaFuncAttributeMaxDynamicSharedMemorySize,
                         ENC_SMEM);
    encoder_h3<<<(N + 63) / 64, 256, ENC_SMEM>>>(pos, benc, N);

    cudaFuncSetAttribute(edge_mma, cudaFuncAttributeMaxDynamicSharedMemorySize,
                         ESMEM);
    int nIter = (E + 15) / 16;
    int grid = nIter < 148 ? nIter : 148;
    edge_mma<<<grid, 512, ESMEM>>>(membs, chebW, gam, bet, alp, chebb, linW,
                                   linb, (float*)d_out, E);
}

// round 15
// speedup vs baseline: 1.0324x; 1.0324x over previous
#include <cuda_runtime.h>
#include <cuda_fp16.h>
#include <math.h>
#include <stdint.h>

#define FDIM 512
#define DDIM 128
#define NMAX 50048
#define EPSF 1e-5f

// Scratch (allocation-free rule: device globals)
__device__ float g_x[(size_t)NMAX * DDIM];      // encoded node features
__device__ unsigned g_Wh[256 * 128];            // W_enc fp16, word = k-pair, [k2][n]

__device__ __forceinline__ void mma16h(float* c, unsigned a0, unsigned a1,
                                       unsigned a2, unsigned a3,
                                       unsigned b0, unsigned b1) {
    asm volatile(
        "mma.sync.aligned.m16n8k16.row.col.f32.f16.f16.f32 "
        "{%0,%1,%2,%3},{%4,%5,%6,%7},{%8,%9},{%0,%1,%2,%3};"
        : "+f"(c[0]), "+f"(c[1]), "+f"(c[2]), "+f"(c[3])
        : "r"(a0), "r"(a1), "r"(a2), "r"(a3), "r"(b0), "r"(b1));
}
__device__ __forceinline__ float clipf(float v) {
    return fminf(1.0f, fmaxf(-1.0f, v));
}
__device__ __forceinline__ unsigned pack2h(float lo, float hi) {
    __half2 h = __floats2half2_rn(lo, hi);
    return *(unsigned*)&h;
}
__device__ __forceinline__ uint32_t smem_u32(const void* p) {
    uint32_t a;
    asm("{ .reg .u64 t; cvta.to.shared.u64 t, %1; cvt.u32.u64 %0, t; }"
        : "=r"(a) : "l"(p));
    return a;
}
__device__ __forceinline__ void cpasync16(uint32_t dst, const void* src, int szr) {
    asm volatile("cp.async.ca.shared.global [%0], [%1], 16, %2;"
                 :: "r"(dst), "l"(src), "r"(szr) : "memory");
}
#define CP_COMMIT() asm volatile("cp.async.commit_group;" ::: "memory")
#define CP_WAIT1()  asm volatile("cp.async.wait_group 1;" ::: "memory")

// ---------------------------------------------------------------------------
// Kernel 0: pack W_enc to fp16 k-pair words over ALL K=512 (256 k2-rows).
// ---------------------------------------------------------------------------
__global__ void prep_w(const float* __restrict__ W) {
    int i = blockIdx.x * blockDim.x + threadIdx.x;
    if (i < 256 * 128) {
        int k2 = i >> 7, n = i & 127;
        g_Wh[i] = pack2h(W[2 * k2 * 128 + n], W[(2 * k2 + 1) * 128 + n]);
    }
}

// ---------------------------------------------------------------------------
// Kernel 1: encoder (unchanged from R13 — M=64 tile, 256 thr, 3 CTAs/SM)
// ---------------------------------------------------------------------------
#define ENC_A_BYTES (64 * 20 * 4)                     // 5120
#define ENC_B_BYTES (16 * 128 * 4)                    // 8192
#define ENC_SMEM    (3 * (ENC_A_BYTES + ENC_B_BYTES)) // 39936

__global__ __launch_bounds__(256, 3)
void encoder_h3(const float* __restrict__ pos, const float* __restrict__ bias,
                int N) {
    extern __shared__ unsigned char sm[];
    unsigned* As = (unsigned*)sm;
    unsigned* Bs = (unsigned*)(sm + 3 * ENC_A_BYTES);
    const uint32_t smb = smem_u32(sm);

    const int t = threadIdx.x, lane = t & 31, w = t >> 5;
    const int lm = lane >> 2, lk = lane & 3;
    const int m0 = (w >> 2) * 32, n0 = (w & 3) * 32;
    const int m0g = blockIdx.x * 64;

    const int arow = t >> 2, aq = t & 3;
    const bool aok = (m0g + arow) < N;
    const float* ap = pos + (size_t)(m0g + arow) * FDIM + aq * 8;
    const int asoff = arow * 20 + aq * 4;
    const int bk2 = t >> 4, bn8 = (t & 15) * 8;
    const int bsw = 8 * (bk2 & 3);
    const uint32_t bdst0 = smb + 3 * ENC_A_BYTES + (bk2 * 128 + (bn8 ^ bsw)) * 4;
    const uint32_t bdst1 = smb + 3 * ENC_A_BYTES + (bk2 * 128 + ((bn8 + 4) ^ bsw)) * 4;
    const unsigned* bsrc = g_Wh + bk2 * 128 + bn8;

    float acc[2][4][4];
#pragma unroll
    for (int mf = 0; mf < 2; mf++)
#pragma unroll
        for (int nf = 0; nf < 4; nf++)
#pragma unroll
            for (int r = 0; r < 4; r++) acc[mf][nf][r] = 0.0f;

    float4 rb0[2], rb1[2];
    auto ldgA = [&](float4* r, int kt) {
        if (aok) {
            r[0] = *(const float4*)(ap + kt * 32);
            r[1] = *(const float4*)(ap + kt * 32 + 4);
        } else {
            r[0] = make_float4(0, 0, 0, 0);
            r[1] = make_float4(0, 0, 0, 0);
        }
    };
    auto stsA = [&](int s, const float4* r) {
        uint4 u = make_uint4(pack2h(r[0].x, r[0].y), pack2h(r[0].z, r[0].w),
                             pack2h(r[1].x, r[1].y), pack2h(r[1].z, r[1].w));
        *(uint4*)&As[s * 1280 + asoff] = u;
    };
    auto cpB = [&](int s, int kt) {
        cpasync16(bdst0 + s * ENC_B_BYTES, bsrc + kt * 16 * 128, 16);
        cpasync16(bdst1 + s * ENC_B_BYTES, bsrc + kt * 16 * 128 + 4, 16);
    };

    ldgA(rb0, 0); ldgA(rb1, 1);
    cpB(0, 0); CP_COMMIT();
    cpB(1, 1); CP_COMMIT();
    stsA(0, rb0); stsA(1, rb1);
    ldgA(rb0, 2); ldgA(rb1, 3);

    for (int kt = 0; kt < 16; kt++) {
        const int s = kt % 3;
        CP_WAIT1();
        __syncthreads();
        if (kt + 2 < 16) {
            float4* rb = (kt & 1) ? rb1 : rb0;
            stsA((kt + 2) % 3, rb);
            cpB((kt + 2) % 3, kt + 2);
            if (kt + 4 < 16) ldgA(rb, kt + 4);
        }
        CP_COMMIT();

        const unsigned* Asp = As + s * 1280;
        const unsigned* Bsp = Bs + s * 2048;
#pragma unroll
        for (int ks = 0; ks < 2; ks++) {
            const int k20 = ks * 8;
            const int sw = 8 * lk;
            unsigned a[2][4];
#pragma unroll
            for (int mf = 0; mf < 2; mf++) {
                int rb_ = m0 + mf * 16;
                a[mf][0] = Asp[(rb_ + lm) * 20 + k20 + lk];
                a[mf][1] = Asp[(rb_ + lm + 8) * 20 + k20 + lk];
                a[mf][2] = Asp[(rb_ + lm) * 20 + k20 + lk + 4];
                a[mf][3] = Asp[(rb_ + lm + 8) * 20 + k20 + lk + 4];
            }
            unsigned b[4][2];
#pragma unroll
            for (int nf = 0; nf < 4; nf++) {
                int cb = n0 + nf * 8;
                b[nf][0] = Bsp[(k20 + lk) * 128 + ((cb + lm) ^ sw)];
                b[nf][1] = Bsp[(k20 + lk + 4) * 128 + ((cb + lm) ^ sw)];
            }
#pragma unroll
            for (int mf = 0; mf < 2; mf++)
#pragma unroll
                for (int nf = 0; nf < 4; nf++)
                    mma16h(acc[mf][nf], a[mf][0], a[mf][1], a[mf][2], a[mf][3],
                           b[nf][0], b[nf][1]);
        }
    }

#pragma unroll
    for (int mf = 0; mf < 2; mf++) {
        int r0 = m0g + m0 + mf * 16 + lm;
#pragma unroll
        for (int nf = 0; nf < 4; nf++) {
            int c = n0 + nf * 8 + 2 * lk;
            float b0 = __ldg(bias + c), b1 = __ldg(bias + c + 1);
            float2 v0, v1;
            v0.x = clipf(acc[mf][nf][0] + b0);
            v0.y = clipf(acc[mf][nf][1] + b1);
            v1.x = clipf(acc[mf][nf][2] + b0);
            v1.y = clipf(acc[mf][nf][3] + b1);
            *(float2*)&g_x[(size_t)r0 * 128 + c]       = v0;
            *(float2*)&g_x[(size_t)(r0 + 8) * 128 + c] = v1;
        }
    }
}

// ---------------------------------------------------------------------------
// Kernel 2: fused per-hyperedge pipeline, 16 edges/iter, FP16 mma m16n8k16.
// R15: stage B reverted to R12 scalar-LDS form (best measured). NEW: the
// stage-A gather is software-pipelined across iterations — member indices
// prefetched during stage B, x-row LDGs issued at end of stage C, so the
// next iteration's stage A is pure ALU+STS (gather latency hidden behind
// stages C/D and the barrier drains).
// smem layout (dynamic, 148480 B): as R12.
// ---------------------------------------------------------------------------
#define ESMEM 148480

__global__ __launch_bounds__(512, 1)
void edge_mma(const int* __restrict__ members, const float* __restrict__ chebW,
              const float* __restrict__ gamma_, const float* __restrict__ beta_,
              const float* __restrict__ alpha_, const float* __restrict__ chebb,
              const float* __restrict__ linW, const float* __restrict__ linb,
              float* __restrict__ out, int E) {
    extern __shared__ unsigned char esm[];
    unsigned* Acs = (unsigned*)esm;
    unsigned* Bcs = (unsigned*)(esm + 32768);
    unsigned* Gw  = (unsigned*)(esm + 65536);
    float*    Hs  = (float*)(esm + 65536);
    unsigned* Sw  = (unsigned*)(esm + 135168);
    float*    Qsm = (float*)(esm + 139520);
    float*    red = (float*)(esm + 148224);

    const int t = threadIdx.x;
    const int lane = t & 31, w = t >> 5;
    const int lm = lane >> 2, lk = lane & 3;

    // ---- fold of prep: A = W0 + W1/7 - 47/49 W2 ; B = -W1/7 + 12/49 W2 ----
    for (int i = t; i < 2048; i += 512) {
        int k2 = i >> 5;
        int cg = (i & 31) * 4;
        const float* p0 = chebW + (2 * k2) * 128 + cg;
        const float* p1 = p0 + 128;
        float4 w00 = __ldg((const float4*)(p0));
        float4 w01 = __ldg((const float4*)(p0 + 16384));
        float4 w02 = __ldg((const float4*)(p0 + 32768));
        float4 w10 = __ldg((const float4*)(p1));
        float4 w11 = __ldg((const float4*)(p1 + 16384));
        float4 w12 = __ldg((const float4*)(p1 + 32768));
        float a0[4] = {w00.x + w01.x*(1.0f/7.0f) - w02.x*(47.0f/49.0f),
                       w00.y + w01.y*(1.0f/7.0f) - w02.y*(47.0f/49.0f),
                       w00.z + w01.z*(1.0f/7.0f) - w02.z*(47.0f/49.0f),
                       w00.w + w01.w*(1.0f/7.0f) - w02.w*(47.0f/49.0f)};
        float a1[4] = {w10.x + w11.x*(1.0f/7.0f) - w12.x*(47.0f/49.0f),
                       w10.y + w11.y*(1.0f/7.0f) - w12.y*(47.0f/49.0f),
                       w10.z + w11.z*(1.0f/7.0f) - w12.z*(47.0f/49.0f),
                       w10.w + w11.w*(1.0f/7.0f) - w12.w*(47.0f/49.0f)};
        float b0[4] = {-w01.x*(1.0f/7.0f) + w02.x*(12.0f/49.0f),
                       -w01.y*(1.0f/7.0f) + w02.y*(12.0f/49.0f),
                       -w01.z*(1.0f/7.0f) + w02.z*(12.0f/49.0f),
                       -w01.w*(1.0f/7.0f) + w02.w*(12.0f/49.0f)};
        float b1[4] = {-w11.x*(1.0f/7.0f) + w12.x*(12.0f/49.0f),
                       -w11.y*(1.0f/7.0f) + w12.y*(12.0f/49.0f),
                       -w11.z*(1.0f/7.0f) + w12.z*(12.0f/49.0f),
                       -w11.w*(1.0f/7.0f) + w12.w*(12.0f/49.0f)};
        int dst = k2 * 128 + (cg ^ (8 * (k2 & 3)));
        uint4 ua = make_uint4(pack2h(a0[0], a1[0]), pack2h(a0[1], a1[1]),
                              pack2h(a0[2], a1[2]), pack2h(a0[3], a1[3]));
        uint4 ub = make_uint4(pack2h(b0[0], b1[0]), pack2h(b0[1], b1[1]),
                              pack2h(b0[2], b1[2]), pack2h(b0[3], b1[3]));
        *(uint4*)&Acs[dst] = ua;
        *(uint4*)&Bcs[dst] = ub;
    }

    const int c4 = t & 31;
    const float4 ga4 = *(const float4*)(gamma_ + 4 * c4);
    const float4 be4 = *(const float4*)(beta_  + 4 * c4);
    const float4 al4 = *(const float4*)(alpha_ + 4 * c4);

    const int d = t & 127, quarter = t >> 7;
    const float lw0 = linW[d], lw1 = linW[128 + d];
    const float lb = __ldg(linb);

    const int m0 = (w >> 2) * 32, n0 = (w & 3) * 32, nq0 = w * 8;
    const int nIter = (E + 15) >> 4;

    __syncthreads();   // Acs/Bcs ready

    // ---- prologue: gather edge data for first iteration ----
    float4 xv[8];
    {
        int it = blockIdx.x;
        if (it < nIter) {
            int e = it * 16 + w;
            int mreg = 0;
            if (lane < 8 && e < E) mreg = __ldg(&members[e * 8 + lane]);
            if (e < E) {
#pragma unroll
                for (int i = 0; i < 8; i++) {
                    int node = __shfl_sync(0xffffffffu, mreg, i);
                    xv[i] = *(const float4*)(g_x + (size_t)node * 128 + 4 * c4);
                }
            }
        }
    }

    for (int it = blockIdx.x; it < nIter; it += gridDim.x) {
        const int ebase = it * 16;
        const int e = ebase + w;

        // ---- stage A: GraphNorm on prefetched xv -> fp16 Gw / Sw ----
        {
            unsigned* grow = Gw + w * 8 * 68 + 2 * c4;
            unsigned* srow = Sw + w * 68 + 2 * c4;
            if (e < E) {
                float4 mean = make_float4(0, 0, 0, 0);
#pragma unroll
                for (int i = 0; i < 8; i++) {
                    mean.x += xv[i].x; mean.y += xv[i].y;
                    mean.z += xv[i].z; mean.w += xv[i].w;
                }
                mean.x *= 0.125f; mean.y *= 0.125f;
                mean.z *= 0.125f; mean.w *= 0.125f;
                float4 am = make_float4(al4.x * mean.x, al4.y * mean.y,
                                        al4.z * mean.z, al4.w * mean.w);
                float4 var = make_float4(0, 0, 0, 0);
#pragma unroll
                for (int i = 0; i < 8; i++) {
                    xv[i].x -= am.x; xv[i].y -= am.y;
                    xv[i].z -= am.z; xv[i].w -= am.w;
                    var.x += xv[i].x * xv[i].x; var.y += xv[i].y * xv[i].y;
                    var.z += xv[i].z * xv[i].z; var.w += xv[i].w * xv[i].w;
                }
                float4 inv;
                inv.x = ga4.x * rsqrtf(var.x * 0.125f + EPSF);
                inv.y = ga4.y * rsqrtf(var.y * 0.125f + EPSF);
                inv.z = ga4.z * rsqrtf(var.z * 0.125f + EPSF);
                inv.w = ga4.w * rsqrtf(var.w * 0.125f + EPSF);
#pragma unroll
                for (int i = 0; i < 8; i++) {
                    uint2 u;
                    u.x = pack2h(xv[i].x * inv.x + be4.x, xv[i].y * inv.y + be4.y);
                    u.y = pack2h(xv[i].z * inv.z + be4.z, xv[i].w * inv.w + be4.w);
                    *(uint2*)(grow + i * 68) = u;
                }
                uint2 su;
                su.x = pack2h(inv.x * 8.0f * mean.x * (1.0f - al4.x) + 8.0f * be4.x,
                              inv.y * 8.0f * mean.y * (1.0f - al4.y) + 8.0f * be4.y);
                su.y = pack2h(inv.z * 8.0f * mean.z * (1.0f - al4.z) + 8.0f * be4.z,
                              inv.w * 8.0f * mean.w * (1.0f - al4.w) + 8.0f * be4.w);
                *(uint2*)srow = su;
            } else {
                uint2 z = make_uint2(0, 0);
#pragma unroll
                for (int i = 0; i < 8; i++) *(uint2*)(grow + i * 68) = z;
                *(uint2*)srow = z;
            }
        }
        __syncthreads();

        // prefetch next iteration's member indices (overlaps stage B)
        const int it2 = it + gridDim.x;
        int mreg2 = 0;
        if (it2 < nIter) {
            int e2 = it2 * 16 + w;
            if (lane < 8 && e2 < E) mreg2 = __ldg(&members[e2 * 8 + lane]);
        }

        // ---- stage B: fp16 MMAs. main: g[128,128]@A ; q: S[16,128]@B ----
        float acc[2][4][4];
        float qac[4];
#pragma unroll
        for (int mf = 0; mf < 2; mf++)
#pragma unroll
            for (int nf = 0; nf < 4; nf++)
#pragma unroll
                for (int r = 0; r < 4; r++) acc[mf][nf][r] = 0.0f;
#pragma unroll
        for (int r = 0; r < 4; r++) qac[r] = 0.0f;

#pragma unroll
        for (int ks = 0; ks < 8; ks++) {
            const int k20 = ks * 8;
            const int sw = 8 * lk;
            unsigned a[2][4];
#pragma unroll
            for (int mf = 0; mf < 2; mf++) {
                int rb = m0 + mf * 16;
                a[mf][0] = Gw[(rb + lm) * 68 + k20 + lk];
                a[mf][1] = Gw[(rb + lm + 8) * 68 + k20 + lk];
                a[mf][2] = Gw[(rb + lm) * 68 + k20 + lk + 4];
                a[mf][3] = Gw[(rb + lm + 8) * 68 + k20 + lk + 4];
            }
            unsigned b[4][2];
#pragma unroll
            for (int nf = 0; nf < 4; nf++) {
                int cb = n0 + nf * 8;
                b[nf][0] = Acs[(k20 + lk) * 128 + ((cb + lm) ^ sw)];
                b[nf][1] = Acs[(k20 + lk + 4) * 128 + ((cb + lm) ^ sw)];
            }
#pragma unroll
            for (int mf = 0; mf < 2; mf++)
#pragma unroll
                for (int nf = 0; nf < 4; nf++)
                    mma16h(acc[mf][nf], a[mf][0], a[mf][1], a[mf][2], a[mf][3],
                           b[nf][0], b[nf][1]);
            unsigned sa0 = Sw[lm * 68 + k20 + lk];
            unsigned sa1 = Sw[(lm + 8) * 68 + k20 + lk];
            unsigned sa2 = Sw[lm * 68 + k20 + lk + 4];
            unsigned sa3 = Sw[(lm + 8) * 68 + k20 + lk + 4];
            unsigned qb0 = Bcs[(k20 + lk) * 128 + ((nq0 + lm) ^ sw)];
            unsigned qb1 = Bcs[(k20 + lk + 4) * 128 + ((nq0 + lm) ^ sw)];
            mma16h(qac, sa0, sa1, sa2, sa3, qb0, qb1);
        }
        {
            int c = nq0 + 2 * lk;
            float cb0 = __ldg(chebb + c), cb1 = __ldg(chebb + c + 1);
            Qsm[lm * 136 + c]           = qac[0] + cb0;
            Qsm[lm * 136 + c + 1]       = qac[1] + cb1;
            Qsm[(lm + 8) * 136 + c]     = qac[2] + cb0;
            Qsm[(lm + 8) * 136 + c + 1] = qac[3] + cb1;
        }
        __syncthreads();

        // ---- stage C: h = clip(acc + Q[e][c]) -> Hs (reuses Gw space) ----
#pragma unroll
        for (int mf = 0; mf < 2; mf++) {
            int rb = m0 + mf * 16 + lm;
            int e0 = rb >> 3;
            int e1 = (rb + 8) >> 3;
#pragma unroll
            for (int nf = 0; nf < 4; nf++) {
                int c = n0 + nf * 8 + 2 * lk;
                float2 q0 = *(const float2*)&Qsm[e0 * 136 + c];
                float2 q1 = *(const float2*)&Qsm[e1 * 136 + c];
                float2 v0, v1;
                v0.x = clipf(acc[mf][nf][0] + q0.x);
                v0.y = clipf(acc[mf][nf][1] + q0.y);
                v1.x = clipf(acc[mf][nf][2] + q1.x);
                v1.y = clipf(acc[mf][nf][3] + q1.y);
                *(float2*)&Hs[rb * 136 + c]       = v0;
                *(float2*)&Hs[(rb + 8) * 136 + c] = v1;
            }
        }

        // issue next iteration's x-row gather (latency hidden behind D + A')
        if (it2 < nIter) {
            int e2 = it2 * 16 + w;
            if (e2 < E) {
#pragma unroll
                for (int i = 0; i < 8; i++) {
                    int node = __shfl_sync(0xffffffffu, mreg2, i);
                    xv[i] = *(const float4*)(g_x + (size_t)node * 128 + 4 * c4);
                }
            }
        }
        __syncthreads();

        // ---- stage D: pooling + linear head + sigmoid (4 edges / thread) ----
        float contrib[4];
#pragma unroll
        for (int j = 0; j < 4; j++) {
            int elj = quarter * 4 + j;
            float mx = -2.0f, mn = 2.0f, ss = 0.0f;
#pragma unroll
            for (int i = 0; i < 8; i++) {
                float h = Hs[(elj * 8 + i) * 136 + d];
                mx = fmaxf(mx, h);
                mn = fminf(mn, h);
                ss += h * h;
            }
            contrib[j] = (mx - mn) * lw0 + sqrtf(ss * 0.125f) * lw1;
        }
#pragma unroll
        for (int j = 0; j < 4; j++) {
            float v = contrib[j];
            v += __shfl_xor_sync(0xffffffffu, v, 16);
            v += __shfl_xor_sync(0xffffffffu, v, 8);
            v += __shfl_xor_sync(0xffffffffu, v, 4);
            v += __shfl_xor_sync(0xffffffffu, v, 2);
            v += __shfl_xor_sync(0xffffffffu, v, 1);
            if (lane == 0) red[(quarter * 4 + j) * 4 + (w & 3)] = v;
        }
        __syncthreads();
        if (t < 16) {
            int eo = ebase + t;
            if (eo < E) {
                float* r = red + t * 4;
                float logit = r[0] + r[1] + r[2] + r[3] + lb;
                out[eo] = 1.0f / (1.0f + expf(-logit));
            }
        }
        __syncthreads();   // protect smem before next iteration
    }
}

// ---------------------------------------------------------------------------
extern "C" void kernel_launch(void* const* d_in, const int* in_sizes, int n_in,
                              void* d_out, int out_size) {
    const float* pos   = (const float*)d_in[0];
    const float* Wenc  = (const float*)d_in[1];
    const float* benc  = (const float*)d_in[2];
    const float* gam   = (const float*)d_in[3];
    const float* bet   = (const float*)d_in[4];
    const float* alp   = (const float*)d_in[5];
    const float* chebW = (const float*)d_in[6];
    const float* chebb = (const float*)d_in[7];
    const float* linW  = (const float*)d_in[8];
    const float* linb  = (const float*)d_in[9];
    const int*   membs = (const int*)d_in[10];

    int N = in_sizes[0] / FDIM;   // 50000
    int E = in_sizes[10] / 8;     // 20000

    prep_w<<<128, 256>>>(Wenc);

    cudaFuncSetAttribute(encoder_h3, cudaFuncAttributeMaxDynamicSharedMemorySize,
                         ENC_SMEM);
    encoder_h3<<<(N + 63) / 64, 256, ENC_SMEM>>>(pos, benc, N);

    cudaFuncSetAttribute(edge_mma, cudaFuncAttributeMaxDynamicSharedMemorySize,
                         ESMEM);
    int nIter = (E + 15) / 16;
    int grid = nIter < 148 ? nIter : 148;
    edge_mma<<<grid, 512, ESMEM>>>(membs, chebW, gam, bet, alp, chebb, linW,
                                   linb, (float*)d_out, E);
}

// round 16
// speedup vs baseline: 1.0429x; 1.0101x over previous
#include <cuda_runtime.h>
#include <cuda_fp16.h>
#include <math.h>
#include <stdint.h>

#define FDIM 512
#define DDIM 128
#define NMAX 50048
#define EPSF 1e-5f

// Scratch (allocation-free rule: device globals)
__device__ float g_x[(size_t)NMAX * DDIM];      // encoded node features
__device__ unsigned g_Wh[256 * 128];            // W_enc fp16, word = k-pair, [k2][n]

__device__ __forceinline__ void mma16h(float* c, unsigned a0, unsigned a1,
                                       unsigned a2, unsigned a3,
                                       unsigned b0, unsigned b1) {
    asm volatile(
        "mma.sync.aligned.m16n8k16.row.col.f32.f16.f16.f32 "
        "{%0,%1,%2,%3},{%4,%5,%6,%7},{%8,%9},{%0,%1,%2,%3};"
        : "+f"(c[0]), "+f"(c[1]), "+f"(c[2]), "+f"(c[3])
        : "r"(a0), "r"(a1), "r"(a2), "r"(a3), "r"(b0), "r"(b1));
}
__device__ __forceinline__ float clipf(float v) {
    return fminf(1.0f, fmaxf(-1.0f, v));
}
__device__ __forceinline__ unsigned pack2h(float lo, float hi) {
    __half2 h = __floats2half2_rn(lo, hi);
    return *(unsigned*)&h;
}
__device__ __forceinline__ uint32_t smem_u32(const void* p) {
    uint32_t a;
    asm("{ .reg .u64 t; cvta.to.shared.u64 t, %1; cvt.u32.u64 %0, t; }"
        : "=r"(a) : "l"(p));
    return a;
}
__device__ __forceinline__ void cpasync16(uint32_t dst, const void* src, int szr) {
    asm volatile("cp.async.ca.shared.global [%0], [%1], 16, %2;"
                 :: "r"(dst), "l"(src), "r"(szr) : "memory");
}
#define CP_COMMIT() asm volatile("cp.async.commit_group;" ::: "memory")
#define CP_WAIT1()  asm volatile("cp.async.wait_group 1;" ::: "memory")

// ---------------------------------------------------------------------------
// Kernel 0: pack W_enc to fp16 k-pair words over ALL K=512 (256 k2-rows):
//   g_Wh[k2*128+n] = (W[2k2][n], W[2k2+1][n])
// ---------------------------------------------------------------------------
__global__ void prep_w(const float* __restrict__ W) {
    int i = blockIdx.x * blockDim.x + threadIdx.x;
    if (i < 256 * 128) {
        int k2 = i >> 7, n = i & 127;
        g_Wh[i] = pack2h(W[2 * k2 * 128 + n], W[(2 * k2 + 1) * 128 + n]);
    }
}

// ---------------------------------------------------------------------------
// Kernel 1: encoder x = clip(pos @ W_enc + b, -1, 1) via FP16 mma m16n8k16.
// CTA tile M=64 x N=128, 256 threads (8 warps, 2x4, warp tile 32x32),
// 3 CTAs/SM. B: cp.async 3-stage from g_Wh. A: fp32 LDG depth-4 register
// prefetch -> pack fp16 -> STS, 3 smem stages. (R13 exact — best measured)
// ---------------------------------------------------------------------------
#define ENC_A_BYTES (64 * 20 * 4)                     // 5120
#define ENC_B_BYTES (16 * 128 * 4)                    // 8192
#define ENC_SMEM    (3 * (ENC_A_BYTES + ENC_B_BYTES)) // 39936

__global__ __launch_bounds__(256, 3)
void encoder_h3(const float* __restrict__ pos, const float* __restrict__ bias,
                int N) {
    extern __shared__ unsigned char sm[];
    unsigned* As = (unsigned*)sm;
    unsigned* Bs = (unsigned*)(sm + 3 * ENC_A_BYTES);
    const uint32_t smb = smem_u32(sm);

    const int t = threadIdx.x, lane = t & 31, w = t >> 5;
    const int lm = lane >> 2, lk = lane & 3;
    const int m0 = (w >> 2) * 32, n0 = (w & 3) * 32;
    const int m0g = blockIdx.x * 64;

    const int arow = t >> 2, aq = t & 3;
    const bool aok = (m0g + arow) < N;
    const float* ap = pos + (size_t)(m0g + arow) * FDIM + aq * 8;
    const int asoff = arow * 20 + aq * 4;
    const int bk2 = t >> 4, bn8 = (t & 15) * 8;
    const int bsw = 8 * (bk2 & 3);
    const uint32_t bdst0 = smb + 3 * ENC_A_BYTES + (bk2 * 128 + (bn8 ^ bsw)) * 4;
    const uint32_t bdst1 = smb + 3 * ENC_A_BYTES + (bk2 * 128 + ((bn8 + 4) ^ bsw)) * 4;
    const unsigned* bsrc = g_Wh + bk2 * 128 + bn8;

    float acc[2][4][4];
#pragma unroll
    for (int mf = 0; mf < 2; mf++)
#pragma unroll
        for (int nf = 0; nf < 4; nf++)
#pragma unroll
            for (int r = 0; r < 4; r++) acc[mf][nf][r] = 0.0f;

    float4 rb0[2], rb1[2];
    auto ldgA = [&](float4* r, int kt) {
        if (aok) {
            r[0] = *(const float4*)(ap + kt * 32);
            r[1] = *(const float4*)(ap + kt * 32 + 4);
        } else {
            r[0] = make_float4(0, 0, 0, 0);
            r[1] = make_float4(0, 0, 0, 0);
        }
    };
    auto stsA = [&](int s, const float4* r) {
        uint4 u = make_uint4(pack2h(r[0].x, r[0].y), pack2h(r[0].z, r[0].w),
                             pack2h(r[1].x, r[1].y), pack2h(r[1].z, r[1].w));
        *(uint4*)&As[s * 1280 + asoff] = u;
    };
    auto cpB = [&](int s, int kt) {
        cpasync16(bdst0 + s * ENC_B_BYTES, bsrc + kt * 16 * 128, 16);
        cpasync16(bdst1 + s * ENC_B_BYTES, bsrc + kt * 16 * 128 + 4, 16);
    };

    ldgA(rb0, 0); ldgA(rb1, 1);
    cpB(0, 0); CP_COMMIT();
    cpB(1, 1); CP_COMMIT();
    stsA(0, rb0); stsA(1, rb1);
    ldgA(rb0, 2); ldgA(rb1, 3);

    for (int kt = 0; kt < 16; kt++) {
        const int s = kt % 3;
        CP_WAIT1();
        __syncthreads();
        if (kt + 2 < 16) {
            float4* rb = (kt & 1) ? rb1 : rb0;
            stsA((kt + 2) % 3, rb);
            cpB((kt + 2) % 3, kt + 2);
            if (kt + 4 < 16) ldgA(rb, kt + 4);
        }
        CP_COMMIT();

        const unsigned* Asp = As + s * 1280;
        const unsigned* Bsp = Bs + s * 2048;
#pragma unroll
        for (int ks = 0; ks < 2; ks++) {
            const int k20 = ks * 8;
            const int sw = 8 * lk;
            unsigned a[2][4];
#pragma unroll
            for (int mf = 0; mf < 2; mf++) {
                int rb_ = m0 + mf * 16;
                a[mf][0] = Asp[(rb_ + lm) * 20 + k20 + lk];
                a[mf][1] = Asp[(rb_ + lm + 8) * 20 + k20 + lk];
                a[mf][2] = Asp[(rb_ + lm) * 20 + k20 + lk + 4];
                a[mf][3] = Asp[(rb_ + lm + 8) * 20 + k20 + lk + 4];
            }
            unsigned b[4][2];
#pragma unroll
            for (int nf = 0; nf < 4; nf++) {
                int cb = n0 + nf * 8;
                b[nf][0] = Bsp[(k20 + lk) * 128 + ((cb + lm) ^ sw)];
                b[nf][1] = Bsp[(k20 + lk + 4) * 128 + ((cb + lm) ^ sw)];
            }
#pragma unroll
            for (int mf = 0; mf < 2; mf++)
#pragma unroll
                for (int nf = 0; nf < 4; nf++)
                    mma16h(acc[mf][nf], a[mf][0], a[mf][1], a[mf][2], a[mf][3],
                           b[nf][0], b[nf][1]);
        }
    }

#pragma unroll
    for (int mf = 0; mf < 2; mf++) {
        int r0 = m0g + m0 + mf * 16 + lm;
#pragma unroll
        for (int nf = 0; nf < 4; nf++) {
            int c = n0 + nf * 8 + 2 * lk;
            float b0 = __ldg(bias + c), b1 = __ldg(bias + c + 1);
            float2 v0, v1;
            v0.x = clipf(acc[mf][nf][0] + b0);
            v0.y = clipf(acc[mf][nf][1] + b1);
            v1.x = clipf(acc[mf][nf][2] + b0);
            v1.y = clipf(acc[mf][nf][3] + b1);
            *(float2*)&g_x[(size_t)r0 * 128 + c]       = v0;
            *(float2*)&g_x[(size_t)(r0 + 8) * 128 + c] = v1;
        }
    }
}

// ---------------------------------------------------------------------------
// Kernel 2: fused per-hyperedge pipeline, 16 edges/iter, FP16 mma m16n8k16.
// (R12/R13 exact — best measured: 50.2us — plus hoisted chebb loads)
// ---------------------------------------------------------------------------
#define ESMEM 148480

__global__ __launch_bounds__(512, 1)
void edge_mma(const int* __restrict__ members, const float* __restrict__ chebW,
              const float* __restrict__ gamma_, const float* __restrict__ beta_,
              const float* __restrict__ alpha_, const float* __restrict__ chebb,
              const float* __restrict__ linW, const float* __restrict__ linb,
              float* __restrict__ out, int E) {
    extern __shared__ unsigned char esm[];
    unsigned* Acs = (unsigned*)esm;
    unsigned* Bcs = (unsigned*)(esm + 32768);
    unsigned* Gw  = (unsigned*)(esm + 65536);
    float*    Hs  = (float*)(esm + 65536);
    unsigned* Sw  = (unsigned*)(esm + 135168);
    float*    Qsm = (float*)(esm + 139520);
    float*    red = (float*)(esm + 148224);

    const int t = threadIdx.x;
    const int lane = t & 31, w = t >> 5;
    const int lm = lane >> 2, lk = lane & 3;

    // ---- fold of prep: A = W0 + W1/7 - 47/49 W2 ; B = -W1/7 + 12/49 W2 ----
    for (int i = t; i < 2048; i += 512) {
        int k2 = i >> 5;
        int cg = (i & 31) * 4;
        const float* p0 = chebW + (2 * k2) * 128 + cg;
        const float* p1 = p0 + 128;
        float4 w00 = __ldg((const float4*)(p0));
        float4 w01 = __ldg((const float4*)(p0 + 16384));
        float4 w02 = __ldg((const float4*)(p0 + 32768));
        float4 w10 = __ldg((const float4*)(p1));
        float4 w11 = __ldg((const float4*)(p1 + 16384));
        float4 w12 = __ldg((const float4*)(p1 + 32768));
        float a0[4] = {w00.x + w01.x*(1.0f/7.0f) - w02.x*(47.0f/49.0f),
                       w00.y + w01.y*(1.0f/7.0f) - w02.y*(47.0f/49.0f),
                       w00.z + w01.z*(1.0f/7.0f) - w02.z*(47.0f/49.0f),
                       w00.w + w01.w*(1.0f/7.0f) - w02.w*(47.0f/49.0f)};
        float a1[4] = {w10.x + w11.x*(1.0f/7.0f) - w12.x*(47.0f/49.0f),
                       w10.y + w11.y*(1.0f/7.0f) - w12.y*(47.0f/49.0f),
                       w10.z + w11.z*(1.0f/7.0f) - w12.z*(47.0f/49.0f),
                       w10.w + w11.w*(1.0f/7.0f) - w12.w*(47.0f/49.0f)};
        float b0[4] = {-w01.x*(1.0f/7.0f) + w02.x*(12.0f/49.0f),
                       -w01.y*(1.0f/7.0f) + w02.y*(12.0f/49.0f),
                       -w01.z*(1.0f/7.0f) + w02.z*(12.0f/49.0f),
                       -w01.w*(1.0f/7.0f) + w02.w*(12.0f/49.0f)};
        float b1[4] = {-w11.x*(1.0f/7.0f) + w12.x*(12.0f/49.0f),
                       -w11.y*(1.0f/7.0f) + w12.y*(12.0f/49.0f),
                       -w11.z*(1.0f/7.0f) + w12.z*(12.0f/49.0f),
                       -w11.w*(1.0f/7.0f) + w12.w*(12.0f/49.0f)};
        int dst = k2 * 128 + (cg ^ (8 * (k2 & 3)));
        uint4 ua = make_uint4(pack2h(a0[0], a1[0]), pack2h(a0[1], a1[1]),
                              pack2h(a0[2], a1[2]), pack2h(a0[3], a1[3]));
        uint4 ub = make_uint4(pack2h(b0[0], b1[0]), pack2h(b0[1], b1[1]),
                              pack2h(b0[2], b1[2]), pack2h(b0[3], b1[3]));
        *(uint4*)&Acs[dst] = ua;
        *(uint4*)&Bcs[dst] = ub;
    }

    const int c4 = t & 31;
    const float4 ga4 = *(const float4*)(gamma_ + 4 * c4);
    const float4 be4 = *(const float4*)(beta_  + 4 * c4);
    const float4 al4 = *(const float4*)(alpha_ + 4 * c4);

    const int d = t & 127, quarter = t >> 7;
    const float lw0 = linW[d], lw1 = linW[128 + d];
    const float lb = __ldg(linb);

    const int m0 = (w >> 2) * 32, n0 = (w & 3) * 32, nq0 = w * 8;
    const int nIter = (E + 15) >> 4;

    // hoisted loop-invariant chebb values for the Qsm write
    const int qc = nq0 + 2 * lk;
    const float qcb0 = __ldg(chebb + qc), qcb1 = __ldg(chebb + qc + 1);

    __syncthreads();   // Acs/Bcs ready

    for (int it = blockIdx.x; it < nIter; it += gridDim.x) {
        const int ebase = it * 16;

        const int el = w;
        const int e = ebase + el;
        int mreg = 0;
        if (lane < 8 && e < E) mreg = __ldg(&members[e * 8 + lane]);

        // ---- stage A: gather + GraphNorm -> fp16 Gw / Sw ----
        {
            unsigned* grow = Gw + el * 8 * 68 + 2 * c4;
            unsigned* srow = Sw + el * 68 + 2 * c4;
            if (e < E) {
                float4 xv[8];
#pragma unroll
                for (int i = 0; i < 8; i++) {
                    int node = __shfl_sync(0xffffffffu, mreg, i);
                    xv[i] = *(const float4*)(g_x + (size_t)node * 128 + 4 * c4);
                }
                float4 mean = make_float4(0, 0, 0, 0);
#pragma unroll
                for (int i = 0; i < 8; i++) {
                    mean.x += xv[i].x; mean.y += xv[i].y;
                    mean.z += xv[i].z; mean.w += xv[i].w;
                }
                mean.x *= 0.125f; mean.y *= 0.125f;
                mean.z *= 0.125f; mean.w *= 0.125f;
                float4 am = make_float4(al4.x * mean.x, al4.y * mean.y,
                                        al4.z * mean.z, al4.w * mean.w);
                float4 var = make_float4(0, 0, 0, 0);
#pragma unroll
                for (int i = 0; i < 8; i++) {
                    xv[i].x -= am.x; xv[i].y -= am.y;
                    xv[i].z -= am.z; xv[i].w -= am.w;
                    var.x += xv[i].x * xv[i].x; var.y += xv[i].y * xv[i].y;
                    var.z += xv[i].z * xv[i].z; var.w += xv[i].w * xv[i].w;
                }
                float4 inv;
                inv.x = ga4.x * rsqrtf(var.x * 0.125f + EPSF);
                inv.y = ga4.y * rsqrtf(var.y * 0.125f + EPSF);
                inv.z = ga4.z * rsqrtf(var.z * 0.125f + EPSF);
                inv.w = ga4.w * rsqrtf(var.w * 0.125f + EPSF);
#pragma unroll
                for (int i = 0; i < 8; i++) {
                    uint2 u;
                    u.x = pack2h(xv[i].x * inv.x + be4.x, xv[i].y * inv.y + be4.y);
                    u.y = pack2h(xv[i].z * inv.z + be4.z, xv[i].w * inv.w + be4.w);
                    *(uint2*)(grow + i * 68) = u;
                }
                uint2 su;
                su.x = pack2h(inv.x * 8.0f * mean.x * (1.0f - al4.x) + 8.0f * be4.x,
                              inv.y * 8.0f * mean.y * (1.0f - al4.y) + 8.0f * be4.y);
                su.y = pack2h(inv.z * 8.0f * mean.z * (1.0f - al4.z) + 8.0f * be4.z,
                              inv.w * 8.0f * mean.w * (1.0f - al4.w) + 8.0f * be4.w);
                *(uint2*)srow = su;
            } else {
                uint2 z = make_uint2(0, 0);
#pragma unroll
                for (int i = 0; i < 8; i++) *(uint2*)(grow + i * 68) = z;
                *(uint2*)srow = z;
            }
        }
        __syncthreads();

        // ---- stage B: fp16 MMAs. main: g[128,128]@A ; q: S[16,128]@B ----
        float acc[2][4][4];
        float qac[4];
#pragma unroll
        for (int mf = 0; mf < 2; mf++)
#pragma unroll
            for (int nf = 0; nf < 4; nf++)
#pragma unroll
                for (int r = 0; r < 4; r++) acc[mf][nf][r] = 0.0f;
#pragma unroll
        for (int r = 0; r < 4; r++) qac[r] = 0.0f;

#pragma unroll
        for (int ks = 0; ks < 8; ks++) {
            const int k20 = ks * 8;
            const int sw = 8 * lk;
            unsigned a[2][4];
#pragma unroll
            for (int mf = 0; mf < 2; mf++) {
                int rb = m0 + mf * 16;
                a[mf][0] = Gw[(rb + lm) * 68 + k20 + lk];
                a[mf][1] = Gw[(rb + lm + 8) * 68 + k20 + lk];
                a[mf][2] = Gw[(rb + lm) * 68 + k20 + lk + 4];
                a[mf][3] = Gw[(rb + lm + 8) * 68 + k20 + lk + 4];
            }
            unsigned b[4][2];
#pragma unroll
            for (int nf = 0; nf < 4; nf++) {
                int cb = n0 + nf * 8;
                b[nf][0] = Acs[(k20 + lk) * 128 + ((cb + lm) ^ sw)];
                b[nf][1] = Acs[(k20 + lk + 4) * 128 + ((cb + lm) ^ sw)];
            }
#pragma unroll
            for (int mf = 0; mf < 2; mf++)
#pragma unroll
                for (int nf = 0; nf < 4; nf++)
                    mma16h(acc[mf][nf], a[mf][0], a[mf][1], a[mf][2], a[mf][3],
                           b[nf][0], b[nf][1]);
            unsigned sa0 = Sw[lm * 68 + k20 + lk];
            unsigned sa1 = Sw[(lm + 8) * 68 + k20 + lk];
            unsigned sa2 = Sw[lm * 68 + k20 + lk + 4];
            unsigned sa3 = Sw[(lm + 8) * 68 + k20 + lk + 4];
            unsigned qb0 = Bcs[(k20 + lk) * 128 + ((nq0 + lm) ^ sw)];
            unsigned qb1 = Bcs[(k20 + lk + 4) * 128 + ((nq0 + lm) ^ sw)];
            mma16h(qac, sa0, sa1, sa2, sa3, qb0, qb1);
        }
        {
            Qsm[lm * 136 + qc]           = qac[0] + qcb0;
            Qsm[lm * 136 + qc + 1]       = qac[1] + qcb1;
            Qsm[(lm + 8) * 136 + qc]     = qac[2] + qcb0;
            Qsm[(lm + 8) * 136 + qc + 1] = qac[3] + qcb1;
        }
        __syncthreads();

        // ---- stage C: h = clip(acc + Q[e][c]) -> Hs (reuses Gw space) ----
#pragma unroll
        for (int mf = 0; mf < 2; mf++) {
            int rb = m0 + mf * 16 + lm;
            int e0 = rb >> 3;
            int e1 = (rb + 8) >> 3;
#pragma unroll
            for (int nf = 0; nf < 4; nf++) {
                int c = n0 + nf * 8 + 2 * lk;
                float2 q0 = *(const float2*)&Qsm[e0 * 136 + c];
                float2 q1 = *(const float2*)&Qsm[e1 * 136 + c];
                float2 v0, v1;
                v0.x = clipf(acc[mf][nf][0] + q0.x);
                v0.y = clipf(acc[mf][nf][1] + q0.y);
                v1.x = clipf(acc[mf][nf][2] + q1.x);
                v1.y = clipf(acc[mf][nf][3] + q1.y);
                *(float2*)&Hs[rb * 136 + c]       = v0;
                *(float2*)&Hs[(rb + 8) * 136 + c] = v1;
            }
        }
        __syncthreads();

        // ---- stage D: pooling + linear head + sigmoid (4 edges / thread) ----
        float contrib[4];
#pragma unroll
        for (int j = 0; j < 4; j++) {
            int elj = quarter * 4 + j;
            float mx = -2.0f, mn = 2.0f, ss = 0.0f;
#pragma unroll
            for (int i = 0; i < 8; i++) {
                float h = Hs[(elj * 8 + i) * 136 + d];
                mx = fmaxf(mx, h);
                mn = fminf(mn, h);
                ss += h * h;
            }
            contrib[j] = (mx - mn) * lw0 + sqrtf(ss * 0.125f) * lw1;
        }
#pragma unroll
        for (int j = 0; j < 4; j++) {
            float v = contrib[j];
            v += __shfl_xor_sync(0xffffffffu, v, 16);
            v += __shfl_xor_sync(0xffffffffu, v, 8);
            v += __shfl_xor_sync(0xffffffffu, v, 4);
            v += __shfl_xor_sync(0xffffffffu, v, 2);
            v += __shfl_xor_sync(0xffffffffu, v, 1);
            if (lane == 0) red[(quarter * 4 + j) * 4 + (w & 3)] = v;
        }
        __syncthreads();
        if (t < 16) {
            int eo = ebase + t;
            if (eo < E) {
                float* r = red + t * 4;
                float logit = r[0] + r[1] + r[2] + r[3] + lb;
                out[eo] = 1.0f / (1.0f + expf(-logit));
            }
        }
        __syncthreads();   // protect smem before next iteration
    }
}

// ---------------------------------------------------------------------------
extern "C" void kernel_launch(void* const* d_in, const int* in_sizes, int n_in,
                              void* d_out, int out_size) {
    const float* pos   = (const float*)d_in[0];
    const float* Wenc  = (const float*)d_in[1];
    const float* benc  = (const float*)d_in[2];
    const float* gam   = (const float*)d_in[3];
    const float* bet   = (const float*)d_in[4];
    const float* alp   = (const float*)d_in[5];
    const float* chebW = (const float*)d_in[6];
    const float* chebb = (const float*)d_in[7];
    const float* linW  = (const float*)d_in[8];
    const float* linb  = (const float*)d_in[9];
    const int*   membs = (const int*)d_in[10];

    int N = in_sizes[0] / FDIM;   // 50000
    int E = in_sizes[10] / 8;     // 20000

    prep_w<<<128, 256>>>(Wenc);

    cudaFuncSetAttribute(encoder_h3, cudaFuncAttributeMaxDynamicSharedMemorySize,
                         ENC_SMEM);
    encoder_h3<<<(N + 63) / 64, 256, ENC_SMEM>>>(pos, benc, N);

    cudaFuncSetAttribute(edge_mma, cudaFuncAttributeMaxDynamicSharedMemorySize,
                         ESMEM);
    int nIter = (E + 15) / 16;
    int grid = nIter < 148 ? nIter : 148;
    edge_mma<<<grid, 512, ESMEM>>>(membs, chebW, gam, bet, alp, chebb, linW,
                                   linb, (float*)d_out, E);
}